// round 2
// baseline (speedup 1.0000x reference)
#include <cuda_runtime.h>
#include <math.h>

// Problem constants (fixed shapes from reference setup_inputs)
#define Bc 16
#define Hc 50
#define Sc 256
#define Dc 256
#define Kc 32
#define SM1 255            // S-1 valid slots after dropping s=0
#define EPSf 1e-12f

// Output layout: [ps_terms (B,H*K,D) | ps_term_mask (B,H*K) | kid (B,H,K) as float]
#define OFF_MASK ((size_t)Bc * Hc * Kc * Dc)            // 6,553,600
#define OFF_KID  (OFF_MASK + (size_t)Bc * Hc * Kc)      // 6,579,200

__device__ __forceinline__ float warp_sum(float v) {
#pragma unroll
    for (int o = 16; o > 0; o >>= 1) v += __shfl_xor_sync(0xffffffffu, v, o);
    return v;
}

__global__ __launch_bounds__(256)
void matching_reducer_kernel(
    const float* __restrict__ sel,    // news_selection_embedding (B,H,S,D)
    const float* __restrict__ txt,    // news_embedding           (B,H,S,D)
    const float* __restrict__ user,   // user_repr                (B,1,D)
    const float* __restrict__ amask,  // his_attn_mask            (B,H,S)
    const int*   __restrict__ rmask,  // his_refined_mask         (B,H,S) int32
    const float* __restrict__ seg,    // segment_embedding        (H,1,D)
    float* __restrict__ out)
{
    const int bh   = blockIdx.x;          // 0 .. B*H-1
    const int b    = bh / Hc;
    const int h    = bh % Hc;
    const int t    = threadIdx.x;
    const int lane = t & 31;
    const int warp = t >> 5;

    __shared__ float q[Dc];
    __shared__ float sgm[Dc];
    __shared__ float scores[SM1 + 1];
    __shared__ float red[8];
    __shared__ unsigned long long redk[8];
    __shared__ int   topidx[Kc];
    __shared__ float topsc[Kc];
    __shared__ float topw[Kc];
    __shared__ float s_invq;

    // Stage q (user vector) and segment row into smem
    q[t]   = user[(size_t)b * Dc + t];
    sgm[t] = seg[(size_t)h * Dc + t];
    __syncthreads();

    // ---- 1/max(||q||, eps) ----
    {
        float v = q[t] * q[t];
        v = warp_sum(v);
        if (lane == 0) red[warp] = v;
        __syncthreads();
        if (t == 0) {
            float s = 0.f;
#pragma unroll
            for (int i = 0; i < 8; i++) s += red[i];
            s_invq = 1.0f / fmaxf(sqrtf(s), EPSf);
        }
        __syncthreads();
    }
    const float invq = s_invq;

    // ---- cosine scores for 255 rows (skip s=0) ----
    const float*  selb = sel + (size_t)bh * Sc * Dc + Dc;   // row s -> original s+1
    const float4* q4   = (const float4*)q;
    const int*    rm   = rmask + (size_t)bh * Sc + 1;

    for (int s = warp; s < SM1; s += 8) {
        const float4* row = (const float4*)(selb + (size_t)s * Dc);
        float dot = 0.f, nrm = 0.f;
#pragma unroll
        for (int i = 0; i < 2; i++) {
            float4 a  = row[lane + i * 32];
            float4 qv = q4[lane + i * 32];
            dot += a.x * qv.x + a.y * qv.y + a.z * qv.z + a.w * qv.w;
            nrm += a.x * a.x + a.y * a.y + a.z * a.z + a.w * a.w;
        }
        dot = warp_sum(dot);
        nrm = warp_sum(nrm);
        if (lane == 0) {
            float sc    = dot * invq / fmaxf(sqrtf(nrm), EPSf);
            bool  valid = (s < Kc) || (rm[s] != 0);
            scores[s]   = valid ? sc : -INFINITY;
        }
    }
    __syncthreads();

    // ---- top-K via 32 rounds of block argmax (score desc, index asc) ----
    for (int k = 0; k < Kc; k++) {
        unsigned long long key = 0ull;
        if (t < SM1) {
            unsigned int fu = __float_as_uint(scores[t]);
            // monotone float -> uint mapping
            unsigned int o = fu ^ ((fu >> 31) ? 0xFFFFFFFFu : 0x80000000u);
            key = ((unsigned long long)o << 32) | (unsigned int)(SM1 - 1 - t);
        }
#pragma unroll
        for (int off = 16; off > 0; off >>= 1) {
            unsigned long long other = __shfl_xor_sync(0xffffffffu, key, off);
            if (other > key) key = other;
        }
        if (lane == 0) redk[warp] = key;
        __syncthreads();
        if (t == 0) {
            unsigned long long m = redk[0];
#pragma unroll
            for (int i = 1; i < 8; i++) if (redk[i] > m) m = redk[i];
            int idx     = SM1 - 1 - (int)(m & 0xFFFFFFFFu);
            topidx[k]   = idx;
            topsc[k]    = scores[idx];
            scores[idx] = -INFINITY;   // remove for next round
        }
        __syncthreads();
    }

    // ---- softmax over the K selected scores (already descending; topsc[0] is max) ----
    if (warp == 0) {
        float e = expf(topsc[lane] - topsc[0]);
        float s = warp_sum(e);
        topw[lane] = e / s;
    }
    __syncthreads();

    // ---- gather + scale + segment add ----
    const float*  txtb = txt + (size_t)bh * Sc * Dc + Dc;
    float4*       outb = (float4*)(out + (size_t)(b * Hc + h) * Kc * Dc);
    const float4* sg4  = (const float4*)sgm;

    for (int k = warp; k < Kc; k += 8) {
        const int   idx = topidx[k];
        const float w   = topw[k];
        const float4* row = (const float4*)(txtb + (size_t)idx * Dc);
        float4*       o4  = outb + (size_t)k * (Dc / 4);
#pragma unroll
        for (int i = 0; i < 2; i++) {
            float4 a  = row[lane + i * 32];
            float4 sv = sg4[lane + i * 32];
            float4 r;
            r.x = a.x * w + sv.x;
            r.y = a.y * w + sv.y;
            r.z = a.z * w + sv.z;
            r.w = a.w * w + sv.w;
            o4[lane + i * 32] = r;
        }
    }

    // ---- mask + kid outputs ----
    if (t < Kc) {
        const size_t oidx = (size_t)(b * Hc + h) * Kc + t;
        const int    idx  = topidx[t];
        out[OFF_MASK + oidx] = amask[(size_t)bh * Sc + 1 + idx];
        out[OFF_KID + oidx]  = (float)idx;
    }
}

extern "C" void kernel_launch(void* const* d_in, const int* in_sizes, int n_in,
                              void* d_out, int out_size)
{
    (void)in_sizes; (void)n_in; (void)out_size;
    const float* sel   = (const float*)d_in[0];
    const float* txt   = (const float*)d_in[1];
    const float* user  = (const float*)d_in[2];
    // d_in[3] = news_repr (unused by reference)
    const float* amask = (const float*)d_in[4];
    const int*   rmask = (const int*)d_in[5];
    const float* seg   = (const float*)d_in[6];
    float* out = (float*)d_out;

    matching_reducer_kernel<<<Bc * Hc, 256>>>(sel, txt, user, amask, rmask, seg, out);
}